// round 5
// baseline (speedup 1.0000x reference)
#include <cuda_runtime.h>
#include <cstdint>
#include <cstddef>

// Problem dims (fixed by the reference)
#define NB    32          // batch
#define TT    2048        // seq
#define MMI   64          // input dim m
#define PPO   64          // output dim p
#define NSTA  512         // state dim n
#define NROWS (NB * TT)   // 65536 flattened (b,t) rows

// Scratch: Bu (input drive) and x (materialized states), 134 MB each.
// __device__ globals are the allowed scratch mechanism (no cudaMalloc).
__device__ float g_Bu[NROWS * NSTA];
__device__ float g_x [NROWS * NSTA];

// ---------------------------------------------------------------------------
// K1: g_Bu[r][n] = sum_m u[r][m] * B[n][m]
//     GEMM M=65536, N=512, K=64. Tile: 128 rows x 64 n per CTA, 256 threads,
//     micro-tile 8x4, K staged through smem in 2 chunks of 32.
// ---------------------------------------------------------------------------
__global__ void __launch_bounds__(256) k_bu(const float* __restrict__ u,
                                            const float* __restrict__ Bm) {
    __shared__ float us[128][33];  // [row][k], pad 33 -> bank = (row + k) % 32
    __shared__ float bs[64][33];   // [n][k]

    const int r0  = blockIdx.x * 128;
    const int n0  = blockIdx.y * 64;
    const int tid = threadIdx.x;
    const int tx  = tid & 15;       // n micro:  p = tx*4 + j
    const int ty  = tid >> 4;       // row micro: r = ty*8 + i
    const int lr  = tid >> 3;       // loader row 0..31
    const int lk  = (tid & 7) * 4;  // loader k offset 0..28

    float acc[8][4];
#pragma unroll
    for (int i = 0; i < 8; i++)
#pragma unroll
        for (int j = 0; j < 4; j++) acc[i][j] = 0.0f;

#pragma unroll
    for (int c = 0; c < 2; c++) {
#pragma unroll
        for (int pass = 0; pass < 4; ++pass) {
            int row = lr + pass * 32;
            float4 v = *reinterpret_cast<const float4*>(
                u + (size_t)(r0 + row) * MMI + c * 32 + lk);
            us[row][lk + 0] = v.x; us[row][lk + 1] = v.y;
            us[row][lk + 2] = v.z; us[row][lk + 3] = v.w;
        }
#pragma unroll
        for (int pass = 0; pass < 2; ++pass) {
            int n = lr + pass * 32;
            float4 v = *reinterpret_cast<const float4*>(
                Bm + (size_t)(n0 + n) * MMI + c * 32 + lk);
            bs[n][lk + 0] = v.x; bs[n][lk + 1] = v.y;
            bs[n][lk + 2] = v.z; bs[n][lk + 3] = v.w;
        }
        __syncthreads();
#pragma unroll
        for (int k = 0; k < 32; k++) {
            float av[8], bv[4];
#pragma unroll
            for (int i = 0; i < 8; i++) av[i] = us[ty * 8 + i][k];
#pragma unroll
            for (int j = 0; j < 4; j++) bv[j] = bs[tx * 4 + j][k];
#pragma unroll
            for (int i = 0; i < 8; i++)
#pragma unroll
                for (int j = 0; j < 4; j++)
                    acc[i][j] = fmaf(av[i], bv[j], acc[i][j]);
        }
        __syncthreads();
    }

#pragma unroll
    for (int i = 0; i < 8; i++) {
        float4 v = make_float4(acc[i][0], acc[i][1], acc[i][2], acc[i][3]);
        *reinterpret_cast<float4*>(
            g_Bu + (size_t)(r0 + ty * 8 + i) * NSTA + n0 + tx * 4) = v;
    }
}

// ---------------------------------------------------------------------------
// K2: sequential companion scan. One CTA per batch, 512 threads.
// State in a smem ring: x_t[i] = r[(h_t + i) & 511], with h_t = (511 - t) & 511.
// Per step:  s = x_{t-1}[511] = r[(511-t)&511]
//            x_t[i] = x_{t-1}[i-1] - a[511-i]*s + bu_t[i]   (i>0)
//            x_t[0] =              - a[511]  *s + bu_t[0]
// Thread i's ring slot (h_t + i) holds exactly x_{t-1}[i-1] before the write,
// so the shift is free. 8-deep register prefetch hides the bu DRAM latency.
// ---------------------------------------------------------------------------
__global__ void __launch_bounds__(512) k_scan(const float* __restrict__ a) {
    const int b = blockIdx.x;
    const int i = threadIdx.x;
    __shared__ float r[512];

    const float naf = -a[511 - i];   // feedback coefficient for position i
    r[i] = 0.0f;

    const float* bu = g_Bu + (size_t)b * (TT * NSTA);
    float*       xo = g_x  + (size_t)b * (TT * NSTA);

    float pf[8];
#pragma unroll
    for (int j = 0; j < 8; j++) pf[j] = bu[(size_t)j * NSTA + i];
    __syncthreads();

    for (int tb = 0; tb < TT; tb += 8) {
#pragma unroll
        for (int j = 0; j < 8; j++) {
            const int t = tb + j;
            const float buv = pf[j];
            if (t + 8 < TT) pf[j] = bu[(size_t)(t + 8) * NSTA + i];

            const int q   = (511 - t) & 511;
            const int pos = (q + i) & 511;
            const float s   = r[q];          // broadcast read of z_{t-1}
            const float old = r[pos];        // own slot: x_{t-1}[i-1]
            __syncthreads();                 // reads done before thread 0 overwrites r[q]

            float v = fmaf(naf, s, buv);
            if (i != 0) v += old;
            r[pos] = v;
            xo[(size_t)t * NSTA + i] = v;
            __syncthreads();                 // writes visible before next step's reads
        }
    }
}

// ---------------------------------------------------------------------------
// K3: y[r][p] = sum_n C[p][n] x[r][n] + sum_m D[p][m] u[r][m]
//     GEMM M=65536, N=64, K=512(+64). Tile 128 rows x 64 p, 256 threads,
//     micro 8x4, K in chunks of 32 (16 chunks from x/C, 2 from u/D).
// ---------------------------------------------------------------------------
__global__ void __launch_bounds__(256) k_out(const float* __restrict__ u,
                                             const float* __restrict__ Cm,
                                             const float* __restrict__ Dm,
                                             float* __restrict__ y) {
    __shared__ float xs[128][33];  // [row][k]
    __shared__ float cs[64][33];   // [p][k]

    const int r0  = blockIdx.x * 128;
    const int tid = threadIdx.x;
    const int tx  = tid & 15;
    const int ty  = tid >> 4;
    const int lr  = tid >> 3;
    const int lk  = (tid & 7) * 4;

    float acc[8][4];
#pragma unroll
    for (int i = 0; i < 8; i++)
#pragma unroll
        for (int j = 0; j < 4; j++) acc[i][j] = 0.0f;

    // ---- 16 chunks over the state dimension n (C * x) ----
    for (int c = 0; c < 16; c++) {
#pragma unroll
        for (int pass = 0; pass < 4; ++pass) {
            int row = lr + pass * 32;
            float4 v = *reinterpret_cast<const float4*>(
                g_x + (size_t)(r0 + row) * NSTA + c * 32 + lk);
            xs[row][lk + 0] = v.x; xs[row][lk + 1] = v.y;
            xs[row][lk + 2] = v.z; xs[row][lk + 3] = v.w;
        }
#pragma unroll
        for (int pass = 0; pass < 2; ++pass) {
            int p = lr + pass * 32;
            float4 v = *reinterpret_cast<const float4*>(
                Cm + (size_t)p * NSTA + c * 32 + lk);
            cs[p][lk + 0] = v.x; cs[p][lk + 1] = v.y;
            cs[p][lk + 2] = v.z; cs[p][lk + 3] = v.w;
        }
        __syncthreads();
#pragma unroll
        for (int k = 0; k < 32; k++) {
            float av[8], bv[4];
#pragma unroll
            for (int i = 0; i < 8; i++) av[i] = xs[ty * 8 + i][k];
#pragma unroll
            for (int j = 0; j < 4; j++) bv[j] = cs[tx * 4 + j][k];
#pragma unroll
            for (int i = 0; i < 8; i++)
#pragma unroll
                for (int j = 0; j < 4; j++)
                    acc[i][j] = fmaf(av[i], bv[j], acc[i][j]);
        }
        __syncthreads();
    }

    // ---- 2 chunks over the input dimension m (D * u) ----
#pragma unroll
    for (int c = 0; c < 2; c++) {
#pragma unroll
        for (int pass = 0; pass < 4; ++pass) {
            int row = lr + pass * 32;
            float4 v = *reinterpret_cast<const float4*>(
                u + (size_t)(r0 + row) * MMI + c * 32 + lk);
            xs[row][lk + 0] = v.x; xs[row][lk + 1] = v.y;
            xs[row][lk + 2] = v.z; xs[row][lk + 3] = v.w;
        }
#pragma unroll
        for (int pass = 0; pass < 2; ++pass) {
            int p = lr + pass * 32;
            float4 v = *reinterpret_cast<const float4*>(
                Dm + (size_t)p * MMI + c * 32 + lk);
            cs[p][lk + 0] = v.x; cs[p][lk + 1] = v.y;
            cs[p][lk + 2] = v.z; cs[p][lk + 3] = v.w;
        }
        __syncthreads();
#pragma unroll
        for (int k = 0; k < 32; k++) {
            float av[8], bv[4];
#pragma unroll
            for (int i = 0; i < 8; i++) av[i] = xs[ty * 8 + i][k];
#pragma unroll
            for (int j = 0; j < 4; j++) bv[j] = cs[tx * 4 + j][k];
#pragma unroll
            for (int i = 0; i < 8; i++)
#pragma unroll
                for (int j = 0; j < 4; j++)
                    acc[i][j] = fmaf(av[i], bv[j], acc[i][j]);
        }
        __syncthreads();
    }

#pragma unroll
    for (int i = 0; i < 8; i++) {
        float4 v = make_float4(acc[i][0], acc[i][1], acc[i][2], acc[i][3]);
        *reinterpret_cast<float4*>(
            y + (size_t)(r0 + ty * 8 + i) * PPO + tx * 4) = v;
    }
}

// ---------------------------------------------------------------------------
// Launch: inputs in metadata order: u, a, B, C, D. Output float32 (b, t, p).
// ---------------------------------------------------------------------------
extern "C" void kernel_launch(void* const* d_in, const int* in_sizes, int n_in,
                              void* d_out, int out_size) {
    const float* u  = (const float*)d_in[0];   // (32, 2048, 64)
    const float* a  = (const float*)d_in[1];   // (512,)
    const float* Bm = (const float*)d_in[2];   // (512, 64)
    const float* Cm = (const float*)d_in[3];   // (64, 512)
    const float* Dm = (const float*)d_in[4];   // (64, 64)
    float* y = (float*)d_out;                  // (32, 2048, 64)

    (void)in_sizes; (void)n_in; (void)out_size;

    // K1: Bu = u @ B^T   (grid: 65536/128 row tiles x 512/64 n tiles)
    k_bu<<<dim3(NROWS / 128, NSTA / 64), 256>>>(u, Bm);

    // K2: sequential companion scan, one CTA per batch
    k_scan<<<NB, 512>>>(a);

    // K3: y = x @ C^T + u @ D^T
    k_out<<<NROWS / 128, 256>>>(u, Cm, Dm, y);
}